// round 14
// baseline (speedup 1.0000x reference)
#include <cuda_runtime.h>
#include <cuda_fp16.h>

// Problem constants
#define NB     64
#define ADJ    1000
#define NN     (NB*ADJ)        // 64000 nodes
#define NE     (1<<20)         // edges
#define MM     32000           // selected pairs
#define DD     128             // feature dim
#define PAD    64              // padded CSR row slots

// ---------------- scratch ----------------------------------------------------
__device__ __align__(16) __half g_x1h  [NN*DD];  // x1 in fp16 (16 MB)
__device__ __align__(16) __half g_agg1h[NN*DD];  // A@x1 in fp16 (16 MB)
__device__ __align__(16) float g_Wc    [DD*DD];
__device__ __align__(16) float g_Wall  [DD*DD];
__device__ __align__(16) float g_Wfi_h [DD*DD];
__device__ __align__(16) float g_Wfi_l [DD*DD];
__device__ __align__(16) float g_Wall_h[DD*DD];
__device__ __align__(16) float g_Wall_l[DD*DD];
__device__ __align__(16) float g_c0  [DD];
__device__ __align__(16) float g_c1  [DD];
__device__ __align__(16) int   g_esrc[NN*PAD];
__device__ __align__(16) int   g_cnt [NN];
__device__ int g_is64;

// ---------------- helpers ----------------------------------------------------
__device__ __forceinline__ long long load_idx(const void* p, long long i, int is64) {
    return is64 ? ((const long long*)p)[i] : (long long)((const int*)p)[i];
}
__device__ __forceinline__ long long clampll(long long v, long long lo, long long hi) {
    return v < lo ? lo : (v > hi ? hi : v);
}
__device__ __forceinline__ int clampi(int v, int hi) {
    return v < 0 ? 0 : (v > hi ? hi : v);
}
__device__ __forceinline__ unsigned tf32_of(float x) {
    unsigned r; asm("cvt.rna.tf32.f32 %0, %1;" : "=r"(r) : "f"(x)); return r;
}
__device__ __forceinline__ void mma_tf32(
    float& c0, float& c1, float& c2, float& c3,
    unsigned a0, unsigned a1, unsigned a2, unsigned a3,
    unsigned b0, unsigned b1)
{
    asm volatile(
        "mma.sync.aligned.m16n8k8.row.col.f32.tf32.tf32.f32 "
        "{%0,%1,%2,%3}, {%4,%5,%6,%7}, {%8,%9}, {%0,%1,%2,%3};"
        : "+f"(c0), "+f"(c1), "+f"(c2), "+f"(c3)
        : "r"(a0), "r"(a1), "r"(a2), "r"(a3), "r"(b0), "r"(b1));
}
// unpack uint2 (4 fp16) and add into float4 accumulator
__device__ __forceinline__ void acc_f16x4(float4& acc, uint2 v) {
    __half2 p0 = *(__half2*)&v.x;
    __half2 p1 = *(__half2*)&v.y;
    float2 f0 = __half22float2(p0);
    float2 f1 = __half22float2(p1);
    acc.x += f0.x; acc.y += f0.y; acc.z += f1.x; acc.w += f1.y;
}
// pair two uint2 (fp16 HADD2), then accumulate into fp32
__device__ __forceinline__ void acc_f16x4_pair(float4& acc, uint2 a, uint2 b) {
    __half2 p0 = __hadd2(*(__half2*)&a.x, *(__half2*)&b.x);
    __half2 p1 = __hadd2(*(__half2*)&a.y, *(__half2*)&b.y);
    float2 f0 = __half22float2(p0);
    float2 f1 = __half22float2(p1);
    acc.x += f0.x; acc.y += f0.y; acc.z += f1.x; acc.w += f1.y;
}

// ---------------- dtype detect + zero cnt ------------------------------------
__global__ void detect_zero_kernel(const unsigned int* __restrict__ e) {
    int i = blockIdx.x * blockDim.x + threadIdx.x;
    if (i == 0) {
        int ok = 1;
        #pragma unroll
        for (int q = 1; q < 64; q += 2) if (e[q] != 0u) ok = 0;
        g_is64 = ok;
    }
    if (i < NN) g_cnt[i] = 0;
}

// ---------------- fp32 -> fp16 conversion ------------------------------------
__global__ __launch_bounds__(256) void conv_f16_kernel(
    const float* __restrict__ X, __half* __restrict__ Y)
{
    int i = blockIdx.x * blockDim.x + threadIdx.x;   // one per 4 elems
    if (i >= NN * DD / 4) return;
    float4 v = __ldg(((const float4*)X) + i);
    __half2 a = __float22half2_rn(make_float2(v.x, v.y));
    __half2 b = __float22half2_rn(make_float2(v.z, v.w));
    uint2 o; o.x = *(unsigned*)&a; o.y = *(unsigned*)&b;
    ((uint2*)Y)[i] = o;
}

// ---------------- padded-CSR fill, 4 edges/thread, vectorized ----------------
__global__ __launch_bounds__(256) void fill_kernel(const void* __restrict__ ei) {
    int base = (blockIdx.x * 256 + threadIdx.x) * 4;
    int is64 = g_is64;
    int src[4], dst[4];
    if (is64) {
        // 4 int64 = 2 int4 loads each for src / dst regions
        const int4* p = (const int4*)ei;
        int4 s0 = __ldg(p + (base >> 1));
        int4 s1 = __ldg(p + (base >> 1) + 1);
        int4 d0 = __ldg(p + ((NE + base) >> 1));
        int4 d1 = __ldg(p + ((NE + base) >> 1) + 1);
        src[0] = s0.x; src[1] = s0.z; src[2] = s1.x; src[3] = s1.z;
        dst[0] = d0.x; dst[1] = d0.z; dst[2] = d1.x; dst[3] = d1.z;
    } else {
        const int* p = (const int*)ei;
        #pragma unroll
        for (int u = 0; u < 4; u++) {
            src[u] = __ldg(p + base + u);
            dst[u] = __ldg(p + NE + base + u);
        }
    }
    #pragma unroll
    for (int u = 0; u < 4; u++) {
        int s = clampi(src[u], NN - 1);
        int d = clampi(dst[u], NN - 1);
        int pos = atomicAdd(&g_cnt[d], 1);
        if (pos < PAD) g_esrc[d * PAD + pos] = s;
    }
}

// ---------------- agg pass 1: fp16 rows, HADD2 pairing, fp32 acc -------------
__global__ __launch_bounds__(256) void agg1h_kernel(
    const __half* __restrict__ Xh, __half* __restrict__ Oh)
{
    int w    = threadIdx.x >> 5;
    int lane = threadIdx.x & 31;
    int n    = blockIdx.x * 8 + w;
    if (n >= NN) return;

    int s0 = n * PAD;
    int cn = min(g_cnt[n], PAD);
    const uint2* __restrict__ Xv = (const uint2*)Xh;

    float4 acc = make_float4(0.f, 0.f, 0.f, 0.f);
    int k = 0;
    for (; k + 8 <= cn; k += 8) {
        int idx[8];
        #pragma unroll
        for (int u = 0; u < 8; u++) idx[u] = __ldg(&g_esrc[s0 + k + u]);
        uint2 v[8];
        #pragma unroll
        for (int u = 0; u < 8; u++) v[u] = __ldg(Xv + (long long)idx[u] * 32 + lane);
        #pragma unroll
        for (int u = 0; u < 8; u += 2) acc_f16x4_pair(acc, v[u], v[u+1]);
    }
    for (; k < cn; k++) {
        int i0 = __ldg(&g_esrc[s0 + k]);
        acc_f16x4(acc, __ldg(Xv + (long long)i0 * 32 + lane));
    }
    __half2 a = __float22half2_rn(make_float2(acc.x, acc.y));
    __half2 b = __float22half2_rn(make_float2(acc.z, acc.w));
    uint2 o; o.x = *(unsigned*)&a; o.y = *(unsigned*)&b;
    ((uint2*)Oh)[(long long)n * 32 + lane] = o;
}

// ---------------- 128x128 weight folds ---------------------------------------
__global__ __launch_bounds__(128) void matmul128(
    const float* __restrict__ A, const float* __restrict__ B,
    const float* __restrict__ avec, const float* __restrict__ addv,
    float* __restrict__ C, float* __restrict__ cvec)
{
    __shared__ __align__(16) float sB[16 * DD];
    int j = threadIdx.x;
    int i = blockIdx.x;
    const float* arow = (i < DD) ? (A + i * DD) : avec;

    float acc = 0.f;
    for (int kc = 0; kc < DD; kc += 16) {
        __syncthreads();
        #pragma unroll
        for (int u = 0; u < 4; u++) {
            int off = u * 128 + j;
            ((float4*)sB)[off] = __ldg(((const float4*)(B + kc * DD)) + off);
        }
        __syncthreads();
        #pragma unroll
        for (int k = 0; k < 16; k++)
            acc = fmaf(__ldg(&arow[kc + k]), sB[k * DD + j], acc);
    }
    if (i < DD) C[i * DD + j] = acc;
    else        cvec[j] = acc + (addv ? __ldg(&addv[j]) : 0.f);
}

// ---------------- tf32 hi/lo split -------------------------------------------
__global__ void split_tf32_kernel(const float* __restrict__ W,
                                  float* __restrict__ hi, float* __restrict__ lo)
{
    int i = blockIdx.x * blockDim.x + threadIdx.x;
    if (i >= DD * DD) return;
    float w  = __ldg(&W[i]);
    float hf = __uint_as_float(tf32_of(w));
    hi[i] = hf;
    lo[i] = __uint_as_float(tf32_of(w - hf));
}

// ---------------- shared MMA core (3xTF32, 64x128 tile from sX) --------------
#define SXP 132
#define SWP 136

__device__ __forceinline__ void mma_tile_and_store(
    float* sX, float* sWh, float* sWl, const int* sIdx,
    const float* __restrict__ Whi, const float* __restrict__ Wlo,
    const float* __restrict__ bias, int use_deg, const float* __restrict__ c1,
    float* __restrict__ out, int m0, int t)
{
    int w    = t >> 5;
    int lane = t & 31;
    int gid  = lane >> 2;
    int tig  = lane & 3;
    int wr   = (w & 3) * 16;
    int wc   = (w >> 2) * 64;

    float c[8][4];
    #pragma unroll
    for (int nt = 0; nt < 8; nt++)
        #pragma unroll
        for (int q = 0; q < 4; q++) c[nt][q] = 0.f;

    for (int kc = 0; kc < DD; kc += 8) {
        __syncthreads();
        {
            int r4 = t >> 5;
            int cc = t & 31;
            *(float4*)(sWh + r4 * SWP + cc * 4) =
                __ldg(((const float4*)(Whi + (kc + r4) * DD)) + cc);
            *(float4*)(sWl + r4 * SWP + cc * 4) =
                __ldg(((const float4*)(Wlo + (kc + r4) * DD)) + cc);
        }
        __syncthreads();

        float x0 = sX[(wr + gid    ) * SXP + kc + tig    ];
        float x1 = sX[(wr + gid + 8) * SXP + kc + tig    ];
        float x2 = sX[(wr + gid    ) * SXP + kc + tig + 4];
        float x3 = sX[(wr + gid + 8) * SXP + kc + tig + 4];
        unsigned ah0 = tf32_of(x0), ah1 = tf32_of(x1), ah2 = tf32_of(x2), ah3 = tf32_of(x3);
        unsigned al0 = tf32_of(x0 - __uint_as_float(ah0));
        unsigned al1 = tf32_of(x1 - __uint_as_float(ah1));
        unsigned al2 = tf32_of(x2 - __uint_as_float(ah2));
        unsigned al3 = tf32_of(x3 - __uint_as_float(ah3));

        #pragma unroll
        for (int nt = 0; nt < 8; nt++) {
            int nb = wc + nt * 8;
            unsigned bh0 = __float_as_uint(sWh[ tig      * SWP + nb + gid]);
            unsigned bh1 = __float_as_uint(sWh[(tig + 4) * SWP + nb + gid]);
            unsigned bl0 = __float_as_uint(sWl[ tig      * SWP + nb + gid]);
            unsigned bl1 = __float_as_uint(sWl[(tig + 4) * SWP + nb + gid]);
            mma_tf32(c[nt][0], c[nt][1], c[nt][2], c[nt][3],
                     ah0, ah1, ah2, ah3, bh0, bh1);
            mma_tf32(c[nt][0], c[nt][1], c[nt][2], c[nt][3],
                     ah0, ah1, ah2, ah3, bl0, bl1);
            mma_tf32(c[nt][0], c[nt][1], c[nt][2], c[nt][3],
                     al0, al1, al2, al3, bh0, bh1);
        }
    }

    int r0l = wr + gid;
    int r1l = r0l + 8;
    float d0 = use_deg ? (float)g_cnt[sIdx[r0l]] : 0.f;
    float d1 = use_deg ? (float)g_cnt[sIdx[r1l]] : 0.f;
    float* orow0 = out + (long long)(m0 + r0l) * DD;
    float* orow1 = out + (long long)(m0 + r1l) * DD;
    #pragma unroll
    for (int nt = 0; nt < 8; nt++) {
        int j0 = wc + nt * 8 + 2 * tig;
        float bv0 = __ldg(&bias[j0]);
        float bv1 = __ldg(&bias[j0 + 1]);
        float cv0 = use_deg ? __ldg(&c1[j0])     : 0.f;
        float cv1 = use_deg ? __ldg(&c1[j0 + 1]) : 0.f;
        float2 o0, o1;
        o0.x = c[nt][0] + bv0 + d0 * cv0;
        o0.y = c[nt][1] + bv1 + d0 * cv1;
        o1.x = c[nt][2] + bv0 + d1 * cv0;
        o1.y = c[nt][3] + bv1 + d1 * cv1;
        *(float2*)(orow0 + j0) = o0;
        *(float2*)(orow1 + j0) = o1;
    }
}

// ---------------- branch 0: gather fp32 rows -> GEMM (tc) --------------------
__global__ __launch_bounds__(256) void gather_mm_tc(
    const float* __restrict__ X, const void* __restrict__ bi,
    const void* __restrict__ ni,
    const float* __restrict__ Whi, const float* __restrict__ Wlo,
    const float* __restrict__ bias, float* __restrict__ out)
{
    __shared__ __align__(16) float sX [64 * SXP];
    __shared__ __align__(16) float sWh[8 * SWP];
    __shared__ __align__(16) float sWl[8 * SWP];
    __shared__ int sIdx[64];

    int t  = threadIdx.x;
    int m0 = blockIdx.x * 64;
    if (t < 64) {
        int is64 = g_is64;
        long long b = clampll(load_idx(bi, m0 + t, is64), 0, NB  - 1);
        long long n = clampll(load_idx(ni, m0 + t, is64), 0, ADJ - 1);
        sIdx[t] = (int)(b * ADJ + n);
    }
    __syncthreads();

    #pragma unroll
    for (int i = 0; i < 8; i++) {
        int u = i * 256 + t;
        int r = u >> 5;
        int c = u & 31;
        float4 v = __ldg(((const float4*)(X + (long long)sIdx[r] * DD)) + c);
        *(float4*)(sX + r * SXP + c * 4) = v;
    }

    mma_tile_and_store(sX, sWh, sWl, sIdx, Whi, Wlo, bias, 0, nullptr, out, m0, t);
}

// ---------------- branch 1 FUSED: aggregate fp16 rows in smem -> GEMM --------
__global__ __launch_bounds__(256) void agg_mm_tc(
    const __half* __restrict__ Xh, const void* __restrict__ bi,
    const void* __restrict__ ni,
    const float* __restrict__ Whi, const float* __restrict__ Wlo,
    const float* __restrict__ bias, const float* __restrict__ c1,
    float* __restrict__ out)
{
    __shared__ __align__(16) float sX [64 * SXP];
    __shared__ __align__(16) float sWh[8 * SWP];
    __shared__ __align__(16) float sWl[8 * SWP];
    __shared__ int sIdx[64];

    int t  = threadIdx.x;
    int m0 = blockIdx.x * 64;
    if (t < 64) {
        int is64 = g_is64;
        long long b = clampll(load_idx(bi, m0 + t, is64), 0, NB  - 1);
        long long n = clampll(load_idx(ni, m0 + t, is64), 0, ADJ - 1);
        sIdx[t] = (int)(b * ADJ + n);
    }
    __syncthreads();

    // aggregate phase: warp w computes rows w*8..w*8+7; lane owns 4 cols (uint2)
    {
        int w    = t >> 5;
        int lane = t & 31;
        const uint2* __restrict__ Xv = (const uint2*)Xh;
        #pragma unroll 1
        for (int q = 0; q < 8; q++) {
            int row = w * 8 + q;
            int n   = sIdx[row];
            int s0  = n * PAD;
            int cn  = min(g_cnt[n], PAD);
            float4 acc = make_float4(0.f, 0.f, 0.f, 0.f);
            int k = 0;
            for (; k + 8 <= cn; k += 8) {
                int idx[8];
                #pragma unroll
                for (int u = 0; u < 8; u++) idx[u] = __ldg(&g_esrc[s0 + k + u]);
                uint2 v[8];
                #pragma unroll
                for (int u = 0; u < 8; u++) v[u] = __ldg(Xv + (long long)idx[u] * 32 + lane);
                #pragma unroll
                for (int u = 0; u < 8; u += 2) acc_f16x4_pair(acc, v[u], v[u+1]);
            }
            for (; k < cn; k++) {
                int i0 = __ldg(&g_esrc[s0 + k]);
                acc_f16x4(acc, __ldg(Xv + (long long)i0 * 32 + lane));
            }
            *(float4*)(sX + row * SXP + lane * 4) = acc;
        }
    }

    mma_tile_and_store(sX, sWh, sWl, sIdx, Whi, Wlo, bias, 1, c1, out, m0, t);
}

// ---------------- launch -----------------------------------------------------
extern "C" void kernel_launch(void* const* d_in, const int* in_sizes, int n_in,
                              void* d_out, int out_size)
{
    const float* x0  = (const float*)d_in[0];
    const float* x1  = (const float*)d_in[1];
    const void*  ei  = d_in[2];
    const void*  b0  = d_in[3];
    const void*  n0  = d_in[4];
    const void*  b1i = d_in[5];
    const void*  n1i = d_in[6];
    const float* W1  = (const float*)d_in[7];
    const float* b1  = (const float*)d_in[8];
    const float* W2  = (const float*)d_in[9];
    const float* b2  = (const float*)d_in[10];
    const float* Wl  = (const float*)d_in[11];
    const float* bl  = (const float*)d_in[12];
    const float* Wfi = (const float*)d_in[13];
    const float* bfi = (const float*)d_in[14];
    float* out = (float*)d_out;

    float *Wc, *Wall, *c0, *c1, *Wfh, *Wfl, *Wah, *Wal;
    __half *x1h, *agg1h;
    cudaGetSymbolAddress((void**)&x1h,   g_x1h);
    cudaGetSymbolAddress((void**)&agg1h, g_agg1h);
    cudaGetSymbolAddress((void**)&Wc,    g_Wc);
    cudaGetSymbolAddress((void**)&Wall,  g_Wall);
    cudaGetSymbolAddress((void**)&c0,    g_c0);
    cudaGetSymbolAddress((void**)&c1,    g_c1);
    cudaGetSymbolAddress((void**)&Wfh,   g_Wfi_h);
    cudaGetSymbolAddress((void**)&Wfl,   g_Wfi_l);
    cudaGetSymbolAddress((void**)&Wah,   g_Wall_h);
    cudaGetSymbolAddress((void**)&Wal,   g_Wall_l);

    static cudaStream_t s2 = nullptr;
    static cudaEvent_t  eA = nullptr, eB = nullptr, eC = nullptr, eD = nullptr;
    if (s2 == nullptr) {
        cudaStreamCreateWithFlags(&s2, cudaStreamNonBlocking);
        cudaEventCreateWithFlags(&eA, cudaEventDisableTiming);
        cudaEventCreateWithFlags(&eB, cudaEventDisableTiming);
        cudaEventCreateWithFlags(&eC, cudaEventDisableTiming);
        cudaEventCreateWithFlags(&eD, cudaEventDisableTiming);
    }

    // #0 main: detect + zero cnt
    detect_zero_kernel<<<(NN + 255) / 256, 256>>>((const unsigned int*)ei);
    cudaEventRecord(eA, 0);

    // #1 s2: x1 -> fp16 (needed by agg1h on main)
    cudaStreamWaitEvent(s2, eA, 0);
    conv_f16_kernel<<<NN * DD / 4 / 256, 256, 0, s2>>>(x1, x1h);
    cudaEventRecord(eC, s2);

    // #2 main: padded-CSR fill
    fill_kernel<<<NE / 1024, 256>>>(ei);

    // #3 main: aggregation pass 1 (fp16 + HADD2 pairing) -- ncu profile slot
    cudaStreamWaitEvent(0, eC, 0);
    agg1h_kernel<<<(NN + 7) / 8, 256>>>(x1h, agg1h);

    // s2: branch-1 weight prep FIRST (agg_mm's only s2 dependency), then branch 0
    matmul128<<<DD + 1, DD, 0, s2>>>(W2, Wl, b2, bl, Wc, c0);                  // #4
    matmul128<<<DD + 1, DD, 0, s2>>>(W1, Wc, b1, nullptr, Wall, c1);           // #5
    split_tf32_kernel<<<DD * DD / 256, 256, 0, s2>>>(Wall, Wah, Wal);          // #6
    cudaEventRecord(eD, s2);
    split_tf32_kernel<<<DD * DD / 256, 256, 0, s2>>>(Wfi, Wfh, Wfl);           // #7
    gather_mm_tc<<<MM / 64, 256, 0, s2>>>(x0, b0, n0, Wfh, Wfl, bfi, out);     // #8
    cudaEventRecord(eB, s2);

    // main: agg_mm waits only on weight folds (eD), NOT on gmm0 -> they overlap
    cudaStreamWaitEvent(0, eD, 0);
    agg_mm_tc<<<MM / 64, 256>>>(agg1h, b1i, n1i, Wah, Wal, c0, c1,
                                out + (long long)MM * DD);                     // #9

    // join s2 into main for capture completeness (graph end = max of both)
    cudaStreamWaitEvent(0, eB, 0);
}

// round 16
// speedup vs baseline: 1.0691x; 1.0691x over previous
#include <cuda_runtime.h>
#include <cuda_fp16.h>

// Problem constants
#define NB     64
#define ADJ    1000
#define NN     (NB*ADJ)        // 64000 nodes
#define NE     (1<<20)         // edges
#define MM     32000           // selected pairs
#define DD     128             // feature dim
#define PAD    64              // padded CSR row slots

// ---------------- scratch ----------------------------------------------------
__device__ __align__(16) __half g_x1h  [NN*DD];  // x1 in fp16 (16 MB)
__device__ __align__(16) __half g_agg1h[NN*DD];  // A@x1 in fp16 (16 MB)
__device__ __align__(16) float g_Wc    [DD*DD];
__device__ __align__(16) float g_Wall  [DD*DD];
__device__ __align__(16) float g_Wfi_h [DD*DD];
__device__ __align__(16) float g_Wfi_l [DD*DD];
__device__ __align__(16) float g_Wall_h[DD*DD];
__device__ __align__(16) float g_Wall_l[DD*DD];
__device__ __align__(16) float g_c0  [DD];
__device__ __align__(16) float g_c1  [DD];
__device__ __align__(16) int   g_esrc[NN*PAD];
__device__ __align__(16) int   g_cnt [NN];
__device__ int g_is64;

// ---------------- helpers ----------------------------------------------------
__device__ __forceinline__ long long load_idx(const void* p, long long i, int is64) {
    return is64 ? ((const long long*)p)[i] : (long long)((const int*)p)[i];
}
__device__ __forceinline__ long long clampll(long long v, long long lo, long long hi) {
    return v < lo ? lo : (v > hi ? hi : v);
}
__device__ __forceinline__ int clampi(int v, int hi) {
    return v < 0 ? 0 : (v > hi ? hi : v);
}
__device__ __forceinline__ unsigned tf32_of(float x) {
    unsigned r; asm("cvt.rna.tf32.f32 %0, %1;" : "=r"(r) : "f"(x)); return r;
}
__device__ __forceinline__ void mma_tf32(
    float& c0, float& c1, float& c2, float& c3,
    unsigned a0, unsigned a1, unsigned a2, unsigned a3,
    unsigned b0, unsigned b1)
{
    asm volatile(
        "mma.sync.aligned.m16n8k8.row.col.f32.tf32.tf32.f32 "
        "{%0,%1,%2,%3}, {%4,%5,%6,%7}, {%8,%9}, {%0,%1,%2,%3};"
        : "+f"(c0), "+f"(c1), "+f"(c2), "+f"(c3)
        : "r"(a0), "r"(a1), "r"(a2), "r"(a3), "r"(b0), "r"(b1));
}
// unpack uint2 (4 fp16) and add into float4 accumulator
__device__ __forceinline__ void acc_f16x4(float4& acc, uint2 v) {
    __half2 p0 = *(__half2*)&v.x;
    __half2 p1 = *(__half2*)&v.y;
    float2 f0 = __half22float2(p0);
    float2 f1 = __half22float2(p1);
    acc.x += f0.x; acc.y += f0.y; acc.z += f1.x; acc.w += f1.y;
}
// pair two uint2 (fp16 HADD2), then accumulate into fp32
__device__ __forceinline__ void acc_f16x4_pair(float4& acc, uint2 a, uint2 b) {
    __half2 p0 = __hadd2(*(__half2*)&a.x, *(__half2*)&b.x);
    __half2 p1 = __hadd2(*(__half2*)&a.y, *(__half2*)&b.y);
    float2 f0 = __half22float2(p0);
    float2 f1 = __half22float2(p1);
    acc.x += f0.x; acc.y += f0.y; acc.z += f1.x; acc.w += f1.y;
}

// ---------------- dtype detect + zero cnt ------------------------------------
__global__ void detect_zero_kernel(const unsigned int* __restrict__ e) {
    int i = blockIdx.x * blockDim.x + threadIdx.x;
    if (i == 0) {
        int ok = 1;
        #pragma unroll
        for (int q = 1; q < 64; q += 2) if (e[q] != 0u) ok = 0;
        g_is64 = ok;
    }
    if (i < NN) g_cnt[i] = 0;
}

// ---------------- fp32 -> fp16 conversion ------------------------------------
__global__ __launch_bounds__(256) void conv_f16_kernel(
    const float* __restrict__ X, __half* __restrict__ Y)
{
    int i = blockIdx.x * blockDim.x + threadIdx.x;   // one per 4 elems
    if (i >= NN * DD / 4) return;
    float4 v = __ldg(((const float4*)X) + i);
    __half2 a = __float22half2_rn(make_float2(v.x, v.y));
    __half2 b = __float22half2_rn(make_float2(v.z, v.w));
    uint2 o; o.x = *(unsigned*)&a; o.y = *(unsigned*)&b;
    ((uint2*)Y)[i] = o;
}

// ---------------- padded-CSR fill, 4 edges/thread, vectorized ----------------
__global__ __launch_bounds__(256) void fill_kernel(const void* __restrict__ ei) {
    int base = (blockIdx.x * 256 + threadIdx.x) * 4;
    int is64 = g_is64;
    int src[4], dst[4];
    if (is64) {
        const int4* p = (const int4*)ei;
        int4 s0 = __ldg(p + (base >> 1));
        int4 s1 = __ldg(p + (base >> 1) + 1);
        int4 d0 = __ldg(p + ((NE + base) >> 1));
        int4 d1 = __ldg(p + ((NE + base) >> 1) + 1);
        src[0] = s0.x; src[1] = s0.z; src[2] = s1.x; src[3] = s1.z;
        dst[0] = d0.x; dst[1] = d0.z; dst[2] = d1.x; dst[3] = d1.z;
    } else {
        const int* p = (const int*)ei;
        #pragma unroll
        for (int u = 0; u < 4; u++) {
            src[u] = __ldg(p + base + u);
            dst[u] = __ldg(p + NE + base + u);
        }
    }
    #pragma unroll
    for (int u = 0; u < 4; u++) {
        int s = clampi(src[u], NN - 1);
        int d = clampi(dst[u], NN - 1);
        int pos = atomicAdd(&g_cnt[d], 1);
        if (pos < PAD) g_esrc[d * PAD + pos] = s;
    }
}

// ---------------- agg pass 1: fp16 rows, int4 indices, HADD2 pairing ---------
__global__ __launch_bounds__(256) void agg1h_kernel(
    const __half* __restrict__ Xh, __half* __restrict__ Oh)
{
    int w    = threadIdx.x >> 5;
    int lane = threadIdx.x & 31;
    int n    = blockIdx.x * 8 + w;
    if (n >= NN) return;

    int s0 = n * PAD;
    int cn = min(g_cnt[n], PAD);
    const uint2* __restrict__ Xv = (const uint2*)Xh;
    const int4*  __restrict__ Ev = (const int4*)(g_esrc + s0);  // 16B-aligned

    float4 acc = make_float4(0.f, 0.f, 0.f, 0.f);
    int k = 0;
    for (; k + 8 <= cn; k += 8) {
        int4 i0 = __ldg(Ev + (k >> 2));
        int4 i1 = __ldg(Ev + (k >> 2) + 1);
        uint2 v[8];
        v[0] = __ldg(Xv + (long long)i0.x * 32 + lane);
        v[1] = __ldg(Xv + (long long)i0.y * 32 + lane);
        v[2] = __ldg(Xv + (long long)i0.z * 32 + lane);
        v[3] = __ldg(Xv + (long long)i0.w * 32 + lane);
        v[4] = __ldg(Xv + (long long)i1.x * 32 + lane);
        v[5] = __ldg(Xv + (long long)i1.y * 32 + lane);
        v[6] = __ldg(Xv + (long long)i1.z * 32 + lane);
        v[7] = __ldg(Xv + (long long)i1.w * 32 + lane);
        #pragma unroll
        for (int u = 0; u < 8; u += 2) acc_f16x4_pair(acc, v[u], v[u+1]);
    }
    for (; k < cn; k++) {
        int i0 = __ldg(&g_esrc[s0 + k]);
        acc_f16x4(acc, __ldg(Xv + (long long)i0 * 32 + lane));
    }
    __half2 a = __float22half2_rn(make_float2(acc.x, acc.y));
    __half2 b = __float22half2_rn(make_float2(acc.z, acc.w));
    uint2 o; o.x = *(unsigned*)&a; o.y = *(unsigned*)&b;
    ((uint2*)Oh)[(long long)n * 32 + lane] = o;
}

// ---------------- 128x128 weight folds ---------------------------------------
__global__ __launch_bounds__(128) void matmul128(
    const float* __restrict__ A, const float* __restrict__ B,
    const float* __restrict__ avec, const float* __restrict__ addv,
    float* __restrict__ C, float* __restrict__ cvec)
{
    __shared__ __align__(16) float sB[16 * DD];
    int j = threadIdx.x;
    int i = blockIdx.x;
    const float* arow = (i < DD) ? (A + i * DD) : avec;

    float acc = 0.f;
    for (int kc = 0; kc < DD; kc += 16) {
        __syncthreads();
        #pragma unroll
        for (int u = 0; u < 4; u++) {
            int off = u * 128 + j;
            ((float4*)sB)[off] = __ldg(((const float4*)(B + kc * DD)) + off);
        }
        __syncthreads();
        #pragma unroll
        for (int k = 0; k < 16; k++)
            acc = fmaf(__ldg(&arow[kc + k]), sB[k * DD + j], acc);
    }
    if (i < DD) C[i * DD + j] = acc;
    else        cvec[j] = acc + (addv ? __ldg(&addv[j]) : 0.f);
}

// ---------------- tf32 hi/lo split -------------------------------------------
__global__ void split_tf32_kernel(const float* __restrict__ W,
                                  float* __restrict__ hi, float* __restrict__ lo)
{
    int i = blockIdx.x * blockDim.x + threadIdx.x;
    if (i >= DD * DD) return;
    float w  = __ldg(&W[i]);
    float hf = __uint_as_float(tf32_of(w));
    hi[i] = hf;
    lo[i] = __uint_as_float(tf32_of(w - hf));
}

// ---------------- shared MMA core (3xTF32, 64x128 tile from sX) --------------
#define SXP 132
#define SWP 136

__device__ __forceinline__ void mma_tile_and_store(
    float* sX, float* sWh, float* sWl, const int* sIdx,
    const float* __restrict__ Whi, const float* __restrict__ Wlo,
    const float* __restrict__ bias, int use_deg, const float* __restrict__ c1,
    float* __restrict__ out, int m0, int t)
{
    int w    = t >> 5;
    int lane = t & 31;
    int gid  = lane >> 2;
    int tig  = lane & 3;
    int wr   = (w & 3) * 16;
    int wc   = (w >> 2) * 64;

    float c[8][4];
    #pragma unroll
    for (int nt = 0; nt < 8; nt++)
        #pragma unroll
        for (int q = 0; q < 4; q++) c[nt][q] = 0.f;

    for (int kc = 0; kc < DD; kc += 8) {
        __syncthreads();
        {
            int r4 = t >> 5;
            int cc = t & 31;
            *(float4*)(sWh + r4 * SWP + cc * 4) =
                __ldg(((const float4*)(Whi + (kc + r4) * DD)) + cc);
            *(float4*)(sWl + r4 * SWP + cc * 4) =
                __ldg(((const float4*)(Wlo + (kc + r4) * DD)) + cc);
        }
        __syncthreads();

        float x0 = sX[(wr + gid    ) * SXP + kc + tig    ];
        float x1 = sX[(wr + gid + 8) * SXP + kc + tig    ];
        float x2 = sX[(wr + gid    ) * SXP + kc + tig + 4];
        float x3 = sX[(wr + gid + 8) * SXP + kc + tig + 4];
        unsigned ah0 = tf32_of(x0), ah1 = tf32_of(x1), ah2 = tf32_of(x2), ah3 = tf32_of(x3);
        unsigned al0 = tf32_of(x0 - __uint_as_float(ah0));
        unsigned al1 = tf32_of(x1 - __uint_as_float(ah1));
        unsigned al2 = tf32_of(x2 - __uint_as_float(ah2));
        unsigned al3 = tf32_of(x3 - __uint_as_float(ah3));

        #pragma unroll
        for (int nt = 0; nt < 8; nt++) {
            int nb = wc + nt * 8;
            unsigned bh0 = __float_as_uint(sWh[ tig      * SWP + nb + gid]);
            unsigned bh1 = __float_as_uint(sWh[(tig + 4) * SWP + nb + gid]);
            unsigned bl0 = __float_as_uint(sWl[ tig      * SWP + nb + gid]);
            unsigned bl1 = __float_as_uint(sWl[(tig + 4) * SWP + nb + gid]);
            mma_tf32(c[nt][0], c[nt][1], c[nt][2], c[nt][3],
                     ah0, ah1, ah2, ah3, bh0, bh1);
            mma_tf32(c[nt][0], c[nt][1], c[nt][2], c[nt][3],
                     ah0, ah1, ah2, ah3, bl0, bl1);
            mma_tf32(c[nt][0], c[nt][1], c[nt][2], c[nt][3],
                     al0, al1, al2, al3, bh0, bh1);
        }
    }

    int r0l = wr + gid;
    int r1l = r0l + 8;
    float d0 = use_deg ? (float)g_cnt[sIdx[r0l]] : 0.f;
    float d1 = use_deg ? (float)g_cnt[sIdx[r1l]] : 0.f;
    float* orow0 = out + (long long)(m0 + r0l) * DD;
    float* orow1 = out + (long long)(m0 + r1l) * DD;
    #pragma unroll
    for (int nt = 0; nt < 8; nt++) {
        int j0 = wc + nt * 8 + 2 * tig;
        float bv0 = __ldg(&bias[j0]);
        float bv1 = __ldg(&bias[j0 + 1]);
        float cv0 = use_deg ? __ldg(&c1[j0])     : 0.f;
        float cv1 = use_deg ? __ldg(&c1[j0 + 1]) : 0.f;
        float2 o0, o1;
        o0.x = c[nt][0] + bv0 + d0 * cv0;
        o0.y = c[nt][1] + bv1 + d0 * cv1;
        o1.x = c[nt][2] + bv0 + d1 * cv0;
        o1.y = c[nt][3] + bv1 + d1 * cv1;
        *(float2*)(orow0 + j0) = o0;
        *(float2*)(orow1 + j0) = o1;
    }
}

// ---------------- branch 0: gather fp32 rows -> GEMM (tc) --------------------
__global__ __launch_bounds__(256) void gather_mm_tc(
    const float* __restrict__ X, const void* __restrict__ bi,
    const void* __restrict__ ni,
    const float* __restrict__ Whi, const float* __restrict__ Wlo,
    const float* __restrict__ bias, float* __restrict__ out)
{
    __shared__ __align__(16) float sX [64 * SXP];
    __shared__ __align__(16) float sWh[8 * SWP];
    __shared__ __align__(16) float sWl[8 * SWP];
    __shared__ int sIdx[64];

    int t  = threadIdx.x;
    int m0 = blockIdx.x * 64;
    if (t < 64) {
        int is64 = g_is64;
        long long b = clampll(load_idx(bi, m0 + t, is64), 0, NB  - 1);
        long long n = clampll(load_idx(ni, m0 + t, is64), 0, ADJ - 1);
        sIdx[t] = (int)(b * ADJ + n);
    }
    __syncthreads();

    #pragma unroll
    for (int i = 0; i < 8; i++) {
        int u = i * 256 + t;
        int r = u >> 5;
        int c = u & 31;
        float4 v = __ldg(((const float4*)(X + (long long)sIdx[r] * DD)) + c);
        *(float4*)(sX + r * SXP + c * 4) = v;
    }

    mma_tile_and_store(sX, sWh, sWl, sIdx, Whi, Wlo, bias, 0, nullptr, out, m0, t);
}

// ---------------- branch 1 FUSED: aggregate fp16 rows in smem -> GEMM --------
__global__ __launch_bounds__(256) void agg_mm_tc(
    const __half* __restrict__ Xh, const void* __restrict__ bi,
    const void* __restrict__ ni,
    const float* __restrict__ Whi, const float* __restrict__ Wlo,
    const float* __restrict__ bias, const float* __restrict__ c1,
    float* __restrict__ out)
{
    __shared__ __align__(16) float sX [64 * SXP];
    __shared__ __align__(16) float sWh[8 * SWP];
    __shared__ __align__(16) float sWl[8 * SWP];
    __shared__ int sIdx[64];

    int t  = threadIdx.x;
    int m0 = blockIdx.x * 64;
    if (t < 64) {
        int is64 = g_is64;
        long long b = clampll(load_idx(bi, m0 + t, is64), 0, NB  - 1);
        long long n = clampll(load_idx(ni, m0 + t, is64), 0, ADJ - 1);
        sIdx[t] = (int)(b * ADJ + n);
    }
    __syncthreads();

    // aggregate phase: warp w computes rows w*8..w*8+7; lane owns 4 cols (uint2)
    {
        int w    = t >> 5;
        int lane = t & 31;
        const uint2* __restrict__ Xv = (const uint2*)Xh;
        #pragma unroll 1
        for (int q = 0; q < 8; q++) {
            int row = w * 8 + q;
            int n   = sIdx[row];
            int s0  = n * PAD;
            int cn  = min(g_cnt[n], PAD);
            const int4* __restrict__ Ev = (const int4*)(g_esrc + s0);
            float4 acc = make_float4(0.f, 0.f, 0.f, 0.f);
            int k = 0;
            for (; k + 8 <= cn; k += 8) {
                int4 i0 = __ldg(Ev + (k >> 2));
                int4 i1 = __ldg(Ev + (k >> 2) + 1);
                uint2 v[8];
                v[0] = __ldg(Xv + (long long)i0.x * 32 + lane);
                v[1] = __ldg(Xv + (long long)i0.y * 32 + lane);
                v[2] = __ldg(Xv + (long long)i0.z * 32 + lane);
                v[3] = __ldg(Xv + (long long)i0.w * 32 + lane);
                v[4] = __ldg(Xv + (long long)i1.x * 32 + lane);
                v[5] = __ldg(Xv + (long long)i1.y * 32 + lane);
                v[6] = __ldg(Xv + (long long)i1.z * 32 + lane);
                v[7] = __ldg(Xv + (long long)i1.w * 32 + lane);
                #pragma unroll
                for (int u = 0; u < 8; u += 2) acc_f16x4_pair(acc, v[u], v[u+1]);
            }
            for (; k < cn; k++) {
                int i0 = __ldg(&g_esrc[s0 + k]);
                acc_f16x4(acc, __ldg(Xv + (long long)i0 * 32 + lane));
            }
            *(float4*)(sX + row * SXP + lane * 4) = acc;
        }
    }

    mma_tile_and_store(sX, sWh, sWl, sIdx, Whi, Wlo, bias, 1, c1, out, m0, t);
}

// ---------------- launch (R13 three-stream schedule restored) -----------------
extern "C" void kernel_launch(void* const* d_in, const int* in_sizes, int n_in,
                              void* d_out, int out_size)
{
    const float* x0  = (const float*)d_in[0];
    const float* x1  = (const float*)d_in[1];
    const void*  ei  = d_in[2];
    const void*  b0  = d_in[3];
    const void*  n0  = d_in[4];
    const void*  b1i = d_in[5];
    const void*  n1i = d_in[6];
    const float* W1  = (const float*)d_in[7];
    const float* b1  = (const float*)d_in[8];
    const float* W2  = (const float*)d_in[9];
    const float* b2  = (const float*)d_in[10];
    const float* Wl  = (const float*)d_in[11];
    const float* bl  = (const float*)d_in[12];
    const float* Wfi = (const float*)d_in[13];
    const float* bfi = (const float*)d_in[14];
    float* out = (float*)d_out;

    float *Wc, *Wall, *c0, *c1, *Wfh, *Wfl, *Wah, *Wal;
    __half *x1h, *agg1h;
    cudaGetSymbolAddress((void**)&x1h,   g_x1h);
    cudaGetSymbolAddress((void**)&agg1h, g_agg1h);
    cudaGetSymbolAddress((void**)&Wc,    g_Wc);
    cudaGetSymbolAddress((void**)&Wall,  g_Wall);
    cudaGetSymbolAddress((void**)&c0,    g_c0);
    cudaGetSymbolAddress((void**)&c1,    g_c1);
    cudaGetSymbolAddress((void**)&Wfh,   g_Wfi_h);
    cudaGetSymbolAddress((void**)&Wfl,   g_Wfi_l);
    cudaGetSymbolAddress((void**)&Wah,   g_Wall_h);
    cudaGetSymbolAddress((void**)&Wal,   g_Wall_l);

    static cudaStream_t s2 = nullptr, s3 = nullptr;
    static cudaEvent_t  eA = nullptr, eB = nullptr, eC = nullptr, eD = nullptr;
    if (s2 == nullptr) {
        cudaStreamCreateWithFlags(&s2, cudaStreamNonBlocking);
        cudaStreamCreateWithFlags(&s3, cudaStreamNonBlocking);
        cudaEventCreateWithFlags(&eA, cudaEventDisableTiming);
        cudaEventCreateWithFlags(&eB, cudaEventDisableTiming);
        cudaEventCreateWithFlags(&eC, cudaEventDisableTiming);
        cudaEventCreateWithFlags(&eD, cudaEventDisableTiming);
    }

    // #0 main: detect + zero cnt
    detect_zero_kernel<<<(NN + 255) / 256, 256>>>((const unsigned int*)ei);
    cudaEventRecord(eA, 0);

    // #1 s2: x1 -> fp16 (needed by agg1h on main)
    cudaStreamWaitEvent(s2, eA, 0);
    conv_f16_kernel<<<NN * DD / 4 / 256, 256, 0, s2>>>(x1, x1h);
    cudaEventRecord(eC, s2);

    // #2 main: padded-CSR fill
    fill_kernel<<<NE / 1024, 256>>>(ei);

    // #3 main: aggregation pass 1 (fp16, int4 idx, HADD2) -- ncu profile slot
    cudaStreamWaitEvent(0, eC, 0);
    agg1h_kernel<<<(NN + 7) / 8, 256>>>(x1h, agg1h);

    // s2 continues: branch 0 (fp32 path)
    split_tf32_kernel<<<DD * DD / 256, 256, 0, s2>>>(Wfi, Wfh, Wfl);           // #4
    gather_mm_tc<<<MM / 64, 256, 0, s2>>>(x0, b0, n0, Wfh, Wfl, bfi, out);     // #5
    cudaEventRecord(eB, s2);

    // s3: weight folds for branch 1
    cudaStreamWaitEvent(s3, eA, 0);
    matmul128<<<DD + 1, DD, 0, s3>>>(W2, Wl, b2, bl, Wc, c0);                  // #6
    matmul128<<<DD + 1, DD, 0, s3>>>(W1, Wc, b1, nullptr, Wall, c1);           // #7
    split_tf32_kernel<<<DD * DD / 256, 256, 0, s3>>>(Wall, Wah, Wal);          // #8
    cudaEventRecord(eD, s3);

    // main: join -> fused branch-1 (aggregate + GEMM)
    cudaStreamWaitEvent(0, eB, 0);
    cudaStreamWaitEvent(0, eD, 0);
    agg_mm_tc<<<MM / 64, 256>>>(agg1h, b1i, n1i, Wah, Wal, c0, c1,
                                out + (long long)MM * DD);                     // #9
}

// round 17
// speedup vs baseline: 1.1292x; 1.0563x over previous
#include <cuda_runtime.h>
#include <cuda_fp16.h>

// Problem constants
#define NB     64
#define ADJ    1000
#define NN     (NB*ADJ)        // 64000 nodes
#define NE     (1<<20)         // edges
#define MM     32000           // selected pairs
#define DD     128             // feature dim
#define PAD    64              // padded CSR row slots

// ---------------- scratch ----------------------------------------------------
__device__ __align__(16) __half g_x1h  [NN*DD];  // x1 in fp16 (16 MB)
__device__ __align__(16) __half g_agg1h[NN*DD];  // A@x1 in fp16 (16 MB)
__device__ __align__(16) float g_Wc    [DD*DD];
__device__ __align__(16) float g_Wall  [DD*DD];
__device__ __align__(16) float g_Wfi_h [DD*DD];
__device__ __align__(16) float g_Wfi_l [DD*DD];
__device__ __align__(16) float g_Wall_h[DD*DD];
__device__ __align__(16) float g_Wall_l[DD*DD];
__device__ __align__(16) float g_c0  [DD];
__device__ __align__(16) float g_c1  [DD];
__device__ __align__(16) int   g_esrc[NN*PAD];
__device__ __align__(16) int   g_cnt [NN];
__device__ int g_is64;

// ---------------- helpers ----------------------------------------------------
__device__ __forceinline__ long long load_idx(const void* p, long long i, int is64) {
    return is64 ? ((const long long*)p)[i] : (long long)((const int*)p)[i];
}
__device__ __forceinline__ long long clampll(long long v, long long lo, long long hi) {
    return v < lo ? lo : (v > hi ? hi : v);
}
__device__ __forceinline__ int clampi(int v, int hi) {
    return v < 0 ? 0 : (v > hi ? hi : v);
}
__device__ __forceinline__ unsigned tf32_of(float x) {
    unsigned r; asm("cvt.rna.tf32.f32 %0, %1;" : "=r"(r) : "f"(x)); return r;
}
__device__ __forceinline__ void mma_tf32(
    float& c0, float& c1, float& c2, float& c3,
    unsigned a0, unsigned a1, unsigned a2, unsigned a3,
    unsigned b0, unsigned b1)
{
    asm volatile(
        "mma.sync.aligned.m16n8k8.row.col.f32.tf32.tf32.f32 "
        "{%0,%1,%2,%3}, {%4,%5,%6,%7}, {%8,%9}, {%0,%1,%2,%3};"
        : "+f"(c0), "+f"(c1), "+f"(c2), "+f"(c3)
        : "r"(a0), "r"(a1), "r"(a2), "r"(a3), "r"(b0), "r"(b1));
}
// unpack uint2 (4 fp16) and add into float4 accumulator
__device__ __forceinline__ void acc_f16x4(float4& acc, uint2 v) {
    __half2 p0 = *(__half2*)&v.x;
    __half2 p1 = *(__half2*)&v.y;
    float2 f0 = __half22float2(p0);
    float2 f1 = __half22float2(p1);
    acc.x += f0.x; acc.y += f0.y; acc.z += f1.x; acc.w += f1.y;
}
// pair two uint2 (fp16 HADD2), then accumulate into fp32
__device__ __forceinline__ void acc_f16x4_pair(float4& acc, uint2 a, uint2 b) {
    __half2 p0 = __hadd2(*(__half2*)&a.x, *(__half2*)&b.x);
    __half2 p1 = __hadd2(*(__half2*)&a.y, *(__half2*)&b.y);
    float2 f0 = __half22float2(p0);
    float2 f1 = __half22float2(p1);
    acc.x += f0.x; acc.y += f0.y; acc.z += f1.x; acc.w += f1.y;
}

// ---------------- dtype detect + zero cnt ------------------------------------
__global__ void detect_zero_kernel(const unsigned int* __restrict__ e) {
    int i = blockIdx.x * blockDim.x + threadIdx.x;
    if (i == 0) {
        int ok = 1;
        #pragma unroll
        for (int q = 1; q < 64; q += 2) if (e[q] != 0u) ok = 0;
        g_is64 = ok;
    }
    if (i < NN) g_cnt[i] = 0;
}

// ---------------- fp32 -> fp16 conversion ------------------------------------
__global__ __launch_bounds__(256) void conv_f16_kernel(
    const float* __restrict__ X, __half* __restrict__ Y)
{
    int i = blockIdx.x * blockDim.x + threadIdx.x;   // one per 4 elems
    if (i >= NN * DD / 4) return;
    float4 v = __ldg(((const float4*)X) + i);
    __half2 a = __float22half2_rn(make_float2(v.x, v.y));
    __half2 b = __float22half2_rn(make_float2(v.z, v.w));
    uint2 o; o.x = *(unsigned*)&a; o.y = *(unsigned*)&b;
    ((uint2*)Y)[i] = o;
}

// ---------------- padded-CSR fill, 4 edges/thread, vectorized ----------------
__global__ __launch_bounds__(256) void fill_kernel(const void* __restrict__ ei) {
    int base = (blockIdx.x * 256 + threadIdx.x) * 4;
    int is64 = g_is64;
    int src[4], dst[4];
    if (is64) {
        const int4* p = (const int4*)ei;
        int4 s0 = __ldg(p + (base >> 1));
        int4 s1 = __ldg(p + (base >> 1) + 1);
        int4 d0 = __ldg(p + ((NE + base) >> 1));
        int4 d1 = __ldg(p + ((NE + base) >> 1) + 1);
        src[0] = s0.x; src[1] = s0.z; src[2] = s1.x; src[3] = s1.z;
        dst[0] = d0.x; dst[1] = d0.z; dst[2] = d1.x; dst[3] = d1.z;
    } else {
        const int* p = (const int*)ei;
        #pragma unroll
        for (int u = 0; u < 4; u++) {
            src[u] = __ldg(p + base + u);
            dst[u] = __ldg(p + NE + base + u);
        }
    }
    #pragma unroll
    for (int u = 0; u < 4; u++) {
        int s = clampi(src[u], NN - 1);
        int d = clampi(dst[u], NN - 1);
        int pos = atomicAdd(&g_cnt[d], 1);
        if (pos < PAD) g_esrc[d * PAD + pos] = s;
    }
}

// ---------------- agg pass 1: fp16 rows, int4 indices, HADD2 pairing ---------
__global__ __launch_bounds__(256) void agg1h_kernel(
    const __half* __restrict__ Xh, __half* __restrict__ Oh)
{
    int w    = threadIdx.x >> 5;
    int lane = threadIdx.x & 31;
    int n    = blockIdx.x * 8 + w;
    if (n >= NN) return;

    int s0 = n * PAD;
    int cn = min(g_cnt[n], PAD);
    const uint2* __restrict__ Xv = (const uint2*)Xh;
    const int4*  __restrict__ Ev = (const int4*)(g_esrc + s0);

    float4 acc = make_float4(0.f, 0.f, 0.f, 0.f);
    int k = 0;
    for (; k + 8 <= cn; k += 8) {
        int4 i0 = __ldg(Ev + (k >> 2));
        int4 i1 = __ldg(Ev + (k >> 2) + 1);
        uint2 v[8];
        v[0] = __ldg(Xv + (long long)i0.x * 32 + lane);
        v[1] = __ldg(Xv + (long long)i0.y * 32 + lane);
        v[2] = __ldg(Xv + (long long)i0.z * 32 + lane);
        v[3] = __ldg(Xv + (long long)i0.w * 32 + lane);
        v[4] = __ldg(Xv + (long long)i1.x * 32 + lane);
        v[5] = __ldg(Xv + (long long)i1.y * 32 + lane);
        v[6] = __ldg(Xv + (long long)i1.z * 32 + lane);
        v[7] = __ldg(Xv + (long long)i1.w * 32 + lane);
        #pragma unroll
        for (int u = 0; u < 8; u += 2) acc_f16x4_pair(acc, v[u], v[u+1]);
    }
    for (; k < cn; k++) {
        int i0 = __ldg(&g_esrc[s0 + k]);
        acc_f16x4(acc, __ldg(Xv + (long long)i0 * 32 + lane));
    }
    __half2 a = __float22half2_rn(make_float2(acc.x, acc.y));
    __half2 b = __float22half2_rn(make_float2(acc.z, acc.w));
    uint2 o; o.x = *(unsigned*)&a; o.y = *(unsigned*)&b;
    ((uint2*)Oh)[(long long)n * 32 + lane] = o;
}

// ---------------- 128x128 weight folds ---------------------------------------
__global__ __launch_bounds__(128) void matmul128(
    const float* __restrict__ A, const float* __restrict__ B,
    const float* __restrict__ avec, const float* __restrict__ addv,
    float* __restrict__ C, float* __restrict__ cvec)
{
    __shared__ __align__(16) float sB[16 * DD];
    int j = threadIdx.x;
    int i = blockIdx.x;
    const float* arow = (i < DD) ? (A + i * DD) : avec;

    float acc = 0.f;
    for (int kc = 0; kc < DD; kc += 16) {
        __syncthreads();
        #pragma unroll
        for (int u = 0; u < 4; u++) {
            int off = u * 128 + j;
            ((float4*)sB)[off] = __ldg(((const float4*)(B + kc * DD)) + off);
        }
        __syncthreads();
        #pragma unroll
        for (int k = 0; k < 16; k++)
            acc = fmaf(__ldg(&arow[kc + k]), sB[k * DD + j], acc);
    }
    if (i < DD) C[i * DD + j] = acc;
    else        cvec[j] = acc + (addv ? __ldg(&addv[j]) : 0.f);
}

// ---------------- tf32 hi/lo split -------------------------------------------
__global__ void split_tf32_kernel(const float* __restrict__ W,
                                  float* __restrict__ hi, float* __restrict__ lo)
{
    int i = blockIdx.x * blockDim.x + threadIdx.x;
    if (i >= DD * DD) return;
    float w  = __ldg(&W[i]);
    float hf = __uint_as_float(tf32_of(w));
    hi[i] = hf;
    lo[i] = __uint_as_float(tf32_of(w - hf));
}

// ---------------- shared MMA core (2xTF32: ah*bh + ah*bl) --------------------
#define SXP 132
#define SWP 136

__device__ __forceinline__ void mma_tile_and_store(
    float* sX, float* sWh, float* sWl, const int* sIdx,
    const float* __restrict__ Whi, const float* __restrict__ Wlo,
    const float* __restrict__ bias, int use_deg, const float* __restrict__ c1,
    float* __restrict__ out, int m0, int t)
{
    int w    = t >> 5;
    int lane = t & 31;
    int gid  = lane >> 2;
    int tig  = lane & 3;
    int wr   = (w & 3) * 16;
    int wc   = (w >> 2) * 64;

    float c[8][4];
    #pragma unroll
    for (int nt = 0; nt < 8; nt++)
        #pragma unroll
        for (int q = 0; q < 4; q++) c[nt][q] = 0.f;

    for (int kc = 0; kc < DD; kc += 8) {
        __syncthreads();
        {
            int r4 = t >> 5;
            int cc = t & 31;
            *(float4*)(sWh + r4 * SWP + cc * 4) =
                __ldg(((const float4*)(Whi + (kc + r4) * DD)) + cc);
            *(float4*)(sWl + r4 * SWP + cc * 4) =
                __ldg(((const float4*)(Wlo + (kc + r4) * DD)) + cc);
        }
        __syncthreads();

        float x0 = sX[(wr + gid    ) * SXP + kc + tig    ];
        float x1 = sX[(wr + gid + 8) * SXP + kc + tig    ];
        float x2 = sX[(wr + gid    ) * SXP + kc + tig + 4];
        float x3 = sX[(wr + gid + 8) * SXP + kc + tig + 4];
        unsigned ah0 = tf32_of(x0), ah1 = tf32_of(x1), ah2 = tf32_of(x2), ah3 = tf32_of(x3);

        #pragma unroll
        for (int nt = 0; nt < 8; nt++) {
            int nb = wc + nt * 8;
            unsigned bh0 = __float_as_uint(sWh[ tig      * SWP + nb + gid]);
            unsigned bh1 = __float_as_uint(sWh[(tig + 4) * SWP + nb + gid]);
            unsigned bl0 = __float_as_uint(sWl[ tig      * SWP + nb + gid]);
            unsigned bl1 = __float_as_uint(sWl[(tig + 4) * SWP + nb + gid]);
            mma_tf32(c[nt][0], c[nt][1], c[nt][2], c[nt][3],
                     ah0, ah1, ah2, ah3, bh0, bh1);                 // hi*hi
            mma_tf32(c[nt][0], c[nt][1], c[nt][2], c[nt][3],
                     ah0, ah1, ah2, ah3, bl0, bl1);                 // hi*lo
        }
    }

    int r0l = wr + gid;
    int r1l = r0l + 8;
    float d0 = use_deg ? (float)g_cnt[sIdx[r0l]] : 0.f;
    float d1 = use_deg ? (float)g_cnt[sIdx[r1l]] : 0.f;
    float* orow0 = out + (long long)(m0 + r0l) * DD;
    float* orow1 = out + (long long)(m0 + r1l) * DD;
    #pragma unroll
    for (int nt = 0; nt < 8; nt++) {
        int j0 = wc + nt * 8 + 2 * tig;
        float bv0 = __ldg(&bias[j0]);
        float bv1 = __ldg(&bias[j0 + 1]);
        float cv0 = use_deg ? __ldg(&c1[j0])     : 0.f;
        float cv1 = use_deg ? __ldg(&c1[j0 + 1]) : 0.f;
        float2 o0, o1;
        o0.x = c[nt][0] + bv0 + d0 * cv0;
        o0.y = c[nt][1] + bv1 + d0 * cv1;
        o1.x = c[nt][2] + bv0 + d1 * cv0;
        o1.y = c[nt][3] + bv1 + d1 * cv1;
        *(float2*)(orow0 + j0) = o0;
        *(float2*)(orow1 + j0) = o1;
    }
}

// ---------------- branch 0: gather fp32 rows -> GEMM (tc) --------------------
__global__ __launch_bounds__(256) void gather_mm_tc(
    const float* __restrict__ X, const void* __restrict__ bi,
    const void* __restrict__ ni,
    const float* __restrict__ Whi, const float* __restrict__ Wlo,
    const float* __restrict__ bias, float* __restrict__ out)
{
    __shared__ __align__(16) float sX [64 * SXP];
    __shared__ __align__(16) float sWh[8 * SWP];
    __shared__ __align__(16) float sWl[8 * SWP];
    __shared__ int sIdx[64];

    int t  = threadIdx.x;
    int m0 = blockIdx.x * 64;
    if (t < 64) {
        int is64 = g_is64;
        long long b = clampll(load_idx(bi, m0 + t, is64), 0, NB  - 1);
        long long n = clampll(load_idx(ni, m0 + t, is64), 0, ADJ - 1);
        sIdx[t] = (int)(b * ADJ + n);
    }
    __syncthreads();

    #pragma unroll
    for (int i = 0; i < 8; i++) {
        int u = i * 256 + t;
        int r = u >> 5;
        int c = u & 31;
        float4 v = __ldg(((const float4*)(X + (long long)sIdx[r] * DD)) + c);
        *(float4*)(sX + r * SXP + c * 4) = v;
    }

    mma_tile_and_store(sX, sWh, sWl, sIdx, Whi, Wlo, bias, 0, nullptr, out, m0, t);
}

// ---------------- branch 1 FUSED: aggregate fp16 rows in smem -> GEMM --------
__global__ __launch_bounds__(256) void agg_mm_tc(
    const __half* __restrict__ Xh, const void* __restrict__ bi,
    const void* __restrict__ ni,
    const float* __restrict__ Whi, const float* __restrict__ Wlo,
    const float* __restrict__ bias, const float* __restrict__ c1,
    float* __restrict__ out)
{
    __shared__ __align__(16) float sX [64 * SXP];
    __shared__ __align__(16) float sWh[8 * SWP];
    __shared__ __align__(16) float sWl[8 * SWP];
    __shared__ int sIdx[64];

    int t  = threadIdx.x;
    int m0 = blockIdx.x * 64;
    if (t < 64) {
        int is64 = g_is64;
        long long b = clampll(load_idx(bi, m0 + t, is64), 0, NB  - 1);
        long long n = clampll(load_idx(ni, m0 + t, is64), 0, ADJ - 1);
        sIdx[t] = (int)(b * ADJ + n);
    }
    __syncthreads();

    // aggregate phase: warp w computes rows w*8..w*8+7; lane owns 4 cols (uint2)
    {
        int w    = t >> 5;
        int lane = t & 31;
        const uint2* __restrict__ Xv = (const uint2*)Xh;
        #pragma unroll 1
        for (int q = 0; q < 8; q++) {
            int row = w * 8 + q;
            int n   = sIdx[row];
            int s0  = n * PAD;
            int cn  = min(g_cnt[n], PAD);
            const int4* __restrict__ Ev = (const int4*)(g_esrc + s0);
            float4 acc = make_float4(0.f, 0.f, 0.f, 0.f);
            int k = 0;
            for (; k + 8 <= cn; k += 8) {
                int4 i0 = __ldg(Ev + (k >> 2));
                int4 i1 = __ldg(Ev + (k >> 2) + 1);
                uint2 v[8];
                v[0] = __ldg(Xv + (long long)i0.x * 32 + lane);
                v[1] = __ldg(Xv + (long long)i0.y * 32 + lane);
                v[2] = __ldg(Xv + (long long)i0.z * 32 + lane);
                v[3] = __ldg(Xv + (long long)i0.w * 32 + lane);
                v[4] = __ldg(Xv + (long long)i1.x * 32 + lane);
                v[5] = __ldg(Xv + (long long)i1.y * 32 + lane);
                v[6] = __ldg(Xv + (long long)i1.z * 32 + lane);
                v[7] = __ldg(Xv + (long long)i1.w * 32 + lane);
                #pragma unroll
                for (int u = 0; u < 8; u += 2) acc_f16x4_pair(acc, v[u], v[u+1]);
            }
            for (; k < cn; k++) {
                int i0 = __ldg(&g_esrc[s0 + k]);
                acc_f16x4(acc, __ldg(Xv + (long long)i0 * 32 + lane));
            }
            *(float4*)(sX + row * SXP + lane * 4) = acc;
        }
    }

    mma_tile_and_store(sX, sWh, sWl, sIdx, Whi, Wlo, bias, 1, c1, out, m0, t);
}

// ---------------- launch (R13/R16 three-stream schedule) ----------------------
extern "C" void kernel_launch(void* const* d_in, const int* in_sizes, int n_in,
                              void* d_out, int out_size)
{
    const float* x0  = (const float*)d_in[0];
    const float* x1  = (const float*)d_in[1];
    const void*  ei  = d_in[2];
    const void*  b0  = d_in[3];
    const void*  n0  = d_in[4];
    const void*  b1i = d_in[5];
    const void*  n1i = d_in[6];
    const float* W1  = (const float*)d_in[7];
    const float* b1  = (const float*)d_in[8];
    const float* W2  = (const float*)d_in[9];
    const float* b2  = (const float*)d_in[10];
    const float* Wl  = (const float*)d_in[11];
    const float* bl  = (const float*)d_in[12];
    const float* Wfi = (const float*)d_in[13];
    const float* bfi = (const float*)d_in[14];
    float* out = (float*)d_out;

    float *Wc, *Wall, *c0, *c1, *Wfh, *Wfl, *Wah, *Wal;
    __half *x1h, *agg1h;
    cudaGetSymbolAddress((void**)&x1h,   g_x1h);
    cudaGetSymbolAddress((void**)&agg1h, g_agg1h);
    cudaGetSymbolAddress((void**)&Wc,    g_Wc);
    cudaGetSymbolAddress((void**)&Wall,  g_Wall);
    cudaGetSymbolAddress((void**)&c0,    g_c0);
    cudaGetSymbolAddress((void**)&c1,    g_c1);
    cudaGetSymbolAddress((void**)&Wfh,   g_Wfi_h);
    cudaGetSymbolAddress((void**)&Wfl,   g_Wfi_l);
    cudaGetSymbolAddress((void**)&Wah,   g_Wall_h);
    cudaGetSymbolAddress((void**)&Wal,   g_Wall_l);

    static cudaStream_t s2 = nullptr, s3 = nullptr;
    static cudaEvent_t  eA = nullptr, eB = nullptr, eC = nullptr, eD = nullptr;
    if (s2 == nullptr) {
        cudaStreamCreateWithFlags(&s2, cudaStreamNonBlocking);
        cudaStreamCreateWithFlags(&s3, cudaStreamNonBlocking);
        cudaEventCreateWithFlags(&eA, cudaEventDisableTiming);
        cudaEventCreateWithFlags(&eB, cudaEventDisableTiming);
        cudaEventCreateWithFlags(&eC, cudaEventDisableTiming);
        cudaEventCreateWithFlags(&eD, cudaEventDisableTiming);
    }

    // #0 main: detect + zero cnt
    detect_zero_kernel<<<(NN + 255) / 256, 256>>>((const unsigned int*)ei);
    cudaEventRecord(eA, 0);

    // #1 s2: x1 -> fp16 (needed by agg1h on main)
    cudaStreamWaitEvent(s2, eA, 0);
    conv_f16_kernel<<<NN * DD / 4 / 256, 256, 0, s2>>>(x1, x1h);
    cudaEventRecord(eC, s2);

    // #2 main: padded-CSR fill
    fill_kernel<<<NE / 1024, 256>>>(ei);

    // #3 main: aggregation pass 1 -- ncu profile slot
    cudaStreamWaitEvent(0, eC, 0);
    agg1h_kernel<<<(NN + 7) / 8, 256>>>(x1h, agg1h);

    // s2 continues: branch 0 (fp32 path)
    split_tf32_kernel<<<DD * DD / 256, 256, 0, s2>>>(Wfi, Wfh, Wfl);           // #4
    gather_mm_tc<<<MM / 64, 256, 0, s2>>>(x0, b0, n0, Wfh, Wfl, bfi, out);     // #5
    cudaEventRecord(eB, s2);

    // s3: weight folds for branch 1
    cudaStreamWaitEvent(s3, eA, 0);
    matmul128<<<DD + 1, DD, 0, s3>>>(W2, Wl, b2, bl, Wc, c0);                  // #6
    matmul128<<<DD + 1, DD, 0, s3>>>(W1, Wc, b1, nullptr, Wall, c1);           // #7
    split_tf32_kernel<<<DD * DD / 256, 256, 0, s3>>>(Wall, Wah, Wal);          // #8
    cudaEventRecord(eD, s3);

    // main: join -> fused branch-1 (aggregate + GEMM)
    cudaStreamWaitEvent(0, eB, 0);
    cudaStreamWaitEvent(0, eD, 0);
    agg_mm_tc<<<MM / 64, 256>>>(agg1h, b1i, n1i, Wah, Wal, c0, c1,
                                out + (long long)MM * DD);                     // #9
}